// round 6
// baseline (speedup 1.0000x reference)
#include <cuda_runtime.h>

// SNNLayer, R6: persistent single-wave version of the R3/R5 dataflow.
//
//   d_in[0] x              : (256,256,1,32)
//   d_in[1] input_matrix   : (256,256,32,32)
//   d_in[2] layer_weights  : (4,256,256,32,32)
//   out                    : (256,256,1,32)
//
// Grid = 148 SMs x 8 CTAs x 4 warps = 4736 persistent warps; each warp
// grid-strides over cells (13-14 cells/warp), eliminating the ~13 wave
// transitions of the 16384-block launch. Loop is unroll-1 so per-iteration
// register pressure is identical to R5 (R4 showed unrolling the cell loop
// starves load batching). Per-cell body unchanged: lane l = (r=l>>3, c=l&7),
// barrier-free, smem-free, all-SHFL cross-lane, LDG.128 streaming loads.

#define NCELLS   65536
#define NDIM     32
#define MAT_F4   256            // 1024 floats = 256 float4
#define WARPS_PER_BLOCK 4
#define THREADS  (WARPS_PER_BLOCK * 32)      // 128
#define NUM_SMS  148
#define CTAS_PER_SM 8
#define BLOCKS   (NUM_SMS * CTAS_PER_SM)     // 1184
#define TOTAL_WARPS (BLOCKS * WARPS_PER_BLOCK)  // 4736
#define DECAY    0.8f
#define FULLMASK 0xFFFFFFFFu

__device__ __forceinline__ void reduce_xor(float4& a)
{
#pragma unroll
    for (int m = 8; m <= 16; m <<= 1) {
        a.x += __shfl_xor_sync(FULLMASK, a.x, m);
        a.y += __shfl_xor_sync(FULLMASK, a.y, m);
        a.z += __shfl_xor_sync(FULLMASK, a.z, m);
        a.w += __shfl_xor_sync(FULLMASK, a.w, m);
    }
}

__global__ __launch_bounds__(THREADS, CTAS_PER_SM)
void snn_layer_kernel(const float* __restrict__ x,
                      const float4* __restrict__ input_matrix,
                      const float4* __restrict__ layer_weights,
                      float4* __restrict__ out)
{
    const int lane = threadIdx.x & 31;
    const int wloc = threadIdx.x >> 5;
    const int r    = lane >> 3;     // row-subgroup 0..3
    const int c    = lane & 7;      // column quad 0..7
    const int wglb = blockIdx.x * WARPS_PER_BLOCK + wloc;   // 0..4735

#pragma unroll 1
    for (int cell = wglb; cell < NCELLS; cell += TOTAL_WARPS) {

        // Lane l holds x[l] for this cell (coalesced 128B per warp).
        const float xreg = x[(size_t)cell * NDIM + lane];

        // ---- Stage 1: act[l] = sum_k x[k] * M[k][l] ----
        const float4* __restrict__ M4 = input_matrix + (size_t)cell * MAT_F4;
        float4 acc = make_float4(0.f, 0.f, 0.f, 0.f);
#pragma unroll
        for (int i = 0; i < 8; ++i) {
            const int k = i * 4 + r;
            const float4 m = __ldcs(&M4[k * 8 + c]);      // 512B coalesced
            const float xv = __shfl_sync(FULLMASK, xreg, k);
            acc.x = fmaf(xv, m.x, acc.x);
            acc.y = fmaf(xv, m.y, acc.y);
            acc.z = fmaf(xv, m.z, acc.z);
            acc.w = fmaf(xv, m.w, acc.w);
        }
        reduce_xor(acc);

        // sel = act[4c + r]  (component r of this lane's reduced quad)
        const float sel = (r == 0) ? acc.x : (r == 1) ? acc.y
                         : (r == 2) ? acc.z : acc.w;

        // Broadcast: av[i] = act[4i + r] (component r of quad i, lane r*8+i)
        float av[8];
#pragma unroll
        for (int i = 0; i < 8; ++i)
            av[i] = __shfl_sync(FULLMASK, sel, (r << 3) + i);

        // ---- Stage 2: acc2[l] = sum_d sum_n act[n] * W_d[n][l] ----
        float4 acc2 = make_float4(0.f, 0.f, 0.f, 0.f);
        const float4* __restrict__ Wc = layer_weights + (size_t)cell * MAT_F4;
#pragma unroll
        for (int d = 0; d < 4; ++d) {
            const float4* __restrict__ Wd = Wc + (size_t)d * NCELLS * MAT_F4;
#pragma unroll
            for (int i = 0; i < 8; ++i) {
                const int n = i * 4 + r;
                const float4 w = __ldcs(&Wd[n * 8 + c]);
                acc2.x = fmaf(av[i], w.x, acc2.x);
                acc2.y = fmaf(av[i], w.y, acc2.y);
                acc2.z = fmaf(av[i], w.z, acc2.z);
                acc2.w = fmaf(av[i], w.w, acc2.w);
            }
        }
        reduce_xor(acc2);

        if (r == 0) {
            acc2.x *= DECAY; acc2.y *= DECAY; acc2.z *= DECAY; acc2.w *= DECAY;
            __stcs(&out[(size_t)cell * 8 + c], acc2);     // 128B coalesced
        }
    }
}

extern "C" void kernel_launch(void* const* d_in, const int* in_sizes, int n_in,
                              void* d_out, int out_size)
{
    const float*  x  = (const float*)d_in[0];
    const float4* im = (const float4*)d_in[1];
    const float4* lw = (const float4*)d_in[2];
    float4* out      = (float4*)d_out;

    snn_layer_kernel<<<BLOCKS, THREADS>>>(x, im, lw, out);
}

// round 7
// speedup vs baseline: 1.0445x; 1.0445x over previous
#include <cuda_runtime.h>

// SNNLayer, R7: R5 dataflow (best: 184.8us, DRAM 91.7%) with 64-thread
// blocks. Per-warp SASS identical to R5 — one cell per warp, barrier-free,
// smem-free, all-SHFL cross-lane, LDG.128 streaming loads. Only change:
// CTA granularity 128->64 threads (32768 blocks), halving the number of
// sibling warps stranded by a CTA's slowest warp at retire and giving the
// HW work-stealer finer units (R4/R6 proved static coarsening regresses).
//
//   d_in[0] x              : (256,256,1,32)
//   d_in[1] input_matrix   : (256,256,32,32)
//   d_in[2] layer_weights  : (4,256,256,32,32)
//   out                    : (256,256,1,32)

#define NCELLS   65536
#define NDIM     32
#define MAT_F4   256            // 1024 floats = 256 float4
#define WARPS_PER_BLOCK 2
#define THREADS  (WARPS_PER_BLOCK * 32)      // 64
#define BLOCKS   (NCELLS / WARPS_PER_BLOCK)  // 32768
#define DECAY    0.8f
#define FULLMASK 0xFFFFFFFFu

__device__ __forceinline__ void reduce_xor(float4& a)
{
#pragma unroll
    for (int m = 8; m <= 16; m <<= 1) {
        a.x += __shfl_xor_sync(FULLMASK, a.x, m);
        a.y += __shfl_xor_sync(FULLMASK, a.y, m);
        a.z += __shfl_xor_sync(FULLMASK, a.z, m);
        a.w += __shfl_xor_sync(FULLMASK, a.w, m);
    }
}

__global__ __launch_bounds__(THREADS, 16)
void snn_layer_kernel(const float* __restrict__ x,
                      const float4* __restrict__ input_matrix,
                      const float4* __restrict__ layer_weights,
                      float4* __restrict__ out)
{
    const int lane = threadIdx.x & 31;
    const int wloc = threadIdx.x >> 5;
    const int r    = lane >> 3;     // row-subgroup 0..3
    const int c    = lane & 7;      // column quad 0..7
    const int cell = blockIdx.x * WARPS_PER_BLOCK + wloc;

    // Lane l holds x[l] for this cell (coalesced 128B per warp).
    const float xreg = x[(size_t)cell * NDIM + lane];

    // ---- Stage 1: act[l] = sum_k x[k] * M[k][l] ----
    const float4* __restrict__ M4 = input_matrix + (size_t)cell * MAT_F4;
    float4 acc = make_float4(0.f, 0.f, 0.f, 0.f);
#pragma unroll
    for (int i = 0; i < 8; ++i) {
        const int k = i * 4 + r;
        const float4 m = __ldcs(&M4[k * 8 + c]);      // 512B coalesced
        const float xv = __shfl_sync(FULLMASK, xreg, k);
        acc.x = fmaf(xv, m.x, acc.x);
        acc.y = fmaf(xv, m.y, acc.y);
        acc.z = fmaf(xv, m.z, acc.z);
        acc.w = fmaf(xv, m.w, acc.w);
    }
    reduce_xor(acc);

    // sel = act[4c + r]  (component r of this lane's reduced quad)
    const float sel = (r == 0) ? acc.x : (r == 1) ? acc.y
                     : (r == 2) ? acc.z : acc.w;

    // Broadcast: av[i] = act[4i + r]  (component r of quad i, lane r*8+i)
    float av[8];
#pragma unroll
    for (int i = 0; i < 8; ++i)
        av[i] = __shfl_sync(FULLMASK, sel, (r << 3) + i);

    // ---- Stage 2: acc2[l] = sum_d sum_n act[n] * W_d[n][l] ----
    float4 acc2 = make_float4(0.f, 0.f, 0.f, 0.f);
    const float4* __restrict__ Wc = layer_weights + (size_t)cell * MAT_F4;
#pragma unroll
    for (int d = 0; d < 4; ++d) {
        const float4* __restrict__ Wd = Wc + (size_t)d * NCELLS * MAT_F4;
#pragma unroll
        for (int i = 0; i < 8; ++i) {
            const int n = i * 4 + r;
            const float4 w = __ldcs(&Wd[n * 8 + c]);  // independent of stage 1
            acc2.x = fmaf(av[i], w.x, acc2.x);
            acc2.y = fmaf(av[i], w.y, acc2.y);
            acc2.z = fmaf(av[i], w.z, acc2.z);
            acc2.w = fmaf(av[i], w.w, acc2.w);
        }
    }
    reduce_xor(acc2);

    if (r == 0) {
        acc2.x *= DECAY; acc2.y *= DECAY; acc2.z *= DECAY; acc2.w *= DECAY;
        out[(size_t)cell * 8 + c] = acc2;             // 128B coalesced
    }
}

extern "C" void kernel_launch(void* const* d_in, const int* in_sizes, int n_in,
                              void* d_out, int out_size)
{
    const float*  x  = (const float*)d_in[0];
    const float4* im = (const float4*)d_in[1];
    const float4* lw = (const float4*)d_in[2];
    float4* out      = (float4*)d_out;

    snn_layer_kernel<<<BLOCKS, THREADS>>>(x, im, lw, out);
}

// round 8
// speedup vs baseline: 1.0447x; 1.0002x over previous
#include <cuda_runtime.h>

// SNNLayer, R8: R5 dataflow (best: 184.8us, block=128) + relaxed register
// cap (6 CTAs/SM -> ~85 regs) + explicit prefetch of the first direction's
// weight tile into registers BEFORE the stage-1 shfl-reduction chain, so
// >=8 LDG.128s are guaranteed in flight across the ~100-cycle reduce/
// broadcast dependency window (previously relied on ptxas hoisting under a
// 64-reg cap that left no room for it).
//
//   d_in[0] x              : (256,256,1,32)
//   d_in[1] input_matrix   : (256,256,32,32)
//   d_in[2] layer_weights  : (4,256,256,32,32)
//   out                    : (256,256,1,32)
//
// Lane l = (r=l>>3, c=l&7); one cell per warp; barrier-free, smem-free.

#define NCELLS   65536
#define NDIM     32
#define MAT_F4   256            // 1024 floats = 256 float4
#define WARPS_PER_BLOCK 4
#define THREADS  (WARPS_PER_BLOCK * 32)      // 128
#define BLOCKS   (NCELLS / WARPS_PER_BLOCK)  // 16384
#define DECAY    0.8f
#define FULLMASK 0xFFFFFFFFu

__device__ __forceinline__ void reduce_xor(float4& a)
{
#pragma unroll
    for (int m = 8; m <= 16; m <<= 1) {
        a.x += __shfl_xor_sync(FULLMASK, a.x, m);
        a.y += __shfl_xor_sync(FULLMASK, a.y, m);
        a.z += __shfl_xor_sync(FULLMASK, a.z, m);
        a.w += __shfl_xor_sync(FULLMASK, a.w, m);
    }
}

__global__ __launch_bounds__(THREADS, 6)
void snn_layer_kernel(const float* __restrict__ x,
                      const float4* __restrict__ input_matrix,
                      const float4* __restrict__ layer_weights,
                      float4* __restrict__ out)
{
    const int lane = threadIdx.x & 31;
    const int wloc = threadIdx.x >> 5;
    const int r    = lane >> 3;     // row-subgroup 0..3
    const int c    = lane & 7;      // column quad 0..7
    const int cell = blockIdx.x * WARPS_PER_BLOCK + wloc;

    // Lane l holds x[l] for this cell (coalesced 128B per warp).
    const float xreg = x[(size_t)cell * NDIM + lane];

    // ---- Stage 1: act[l] = sum_k x[k] * M[k][l] ----
    const float4* __restrict__ M4 = input_matrix + (size_t)cell * MAT_F4;
    float4 acc = make_float4(0.f, 0.f, 0.f, 0.f);
#pragma unroll
    for (int i = 0; i < 8; ++i) {
        const int k = i * 4 + r;
        const float4 m = __ldcs(&M4[k * 8 + c]);      // 512B coalesced
        const float xv = __shfl_sync(FULLMASK, xreg, k);
        acc.x = fmaf(xv, m.x, acc.x);
        acc.y = fmaf(xv, m.y, acc.y);
        acc.z = fmaf(xv, m.z, acc.z);
        acc.w = fmaf(xv, m.w, acc.w);
    }

    // Prefetch direction-0 weights NOW — these 8 LDG.128s are independent of
    // the reduction below and keep the warp's memory pipe busy through it.
    const float4* __restrict__ Wc = layer_weights + (size_t)cell * MAT_F4;
    float4 w0[8];
#pragma unroll
    for (int i = 0; i < 8; ++i)
        w0[i] = __ldcs(&Wc[(i * 4 + r) * 8 + c]);

    reduce_xor(acc);

    // sel = act[4c + r]  (component r of this lane's reduced quad)
    const float sel = (r == 0) ? acc.x : (r == 1) ? acc.y
                     : (r == 2) ? acc.z : acc.w;

    // Broadcast: av[i] = act[4i + r]  (component r of quad i, lane r*8+i)
    float av[8];
#pragma unroll
    for (int i = 0; i < 8; ++i)
        av[i] = __shfl_sync(FULLMASK, sel, (r << 3) + i);

    // ---- Stage 2: acc2[l] = sum_d sum_n act[n] * W_d[n][l] ----
    float4 acc2 = make_float4(0.f, 0.f, 0.f, 0.f);

    // Direction 0 from the prefetched registers.
#pragma unroll
    for (int i = 0; i < 8; ++i) {
        acc2.x = fmaf(av[i], w0[i].x, acc2.x);
        acc2.y = fmaf(av[i], w0[i].y, acc2.y);
        acc2.z = fmaf(av[i], w0[i].z, acc2.z);
        acc2.w = fmaf(av[i], w0[i].w, acc2.w);
    }

    // Directions 1..3 streamed.
#pragma unroll
    for (int d = 1; d < 4; ++d) {
        const float4* __restrict__ Wd = Wc + (size_t)d * NCELLS * MAT_F4;
#pragma unroll
        for (int i = 0; i < 8; ++i) {
            const float4 w = __ldcs(&Wd[(i * 4 + r) * 8 + c]);
            acc2.x = fmaf(av[i], w.x, acc2.x);
            acc2.y = fmaf(av[i], w.y, acc2.y);
            acc2.z = fmaf(av[i], w.z, acc2.z);
            acc2.w = fmaf(av[i], w.w, acc2.w);
        }
    }
    reduce_xor(acc2);

    if (r == 0) {
        acc2.x *= DECAY; acc2.y *= DECAY; acc2.z *= DECAY; acc2.w *= DECAY;
        out[(size_t)cell * 8 + c] = acc2;             // 128B coalesced
    }
}

extern "C" void kernel_launch(void* const* d_in, const int* in_sizes, int n_in,
                              void* d_out, int out_size)
{
    const float*  x  = (const float*)d_in[0];
    const float4* im = (const float4*)d_in[1];
    const float4* lw = (const float4*)d_in[2];
    float4* out      = (float4*)d_out;

    snn_layer_kernel<<<BLOCKS, THREADS>>>(x, im, lw, out);
}